// round 15
// baseline (speedup 1.0000x reference)
#include <cuda_runtime.h>
#include <math.h>

#define B_   32
#define T_   64
#define BT   2048            // B*T
#define IND  4894
#define E_   128
#define G3   384             // 3*H
#define NG   768             // both GRUs' gates
#define WPAD 132             // smem stride for Whh rows (conflict-free float4)
#define GRU_SMEM  (G3 * WPAD * 4)    // 202752 B
#define ATTN_SMEM (E_ * E_ * 4)      // 65536 B (W_beta interleaved)
#define HST  36              // sh_h row stride (32 rows + pad, conflict-free)

typedef unsigned long long u64;

// ---------------- device scratch (no allocations allowed) ----------------
__device__ float g_emb[BT * E_];        // emb[m][e]  (atomicAdd target)
__device__ float g_GI [BT * NG];        // input gates + bih (+ bhh for r,z)
__device__ float g_Wbeta2[E_ * E_];     // [kk][(e&31)*4 + (e>>5)]
__device__ float g_Hb[BT * T_ * E_];    // hb states [b][i][k][e]
__device__ float g_S [BT * T_];         // scores [b][i][k]

__device__ __forceinline__ float fast_tanh(float x) {
    float y; asm("tanh.approx.f32 %0, %1;" : "=f"(y) : "f"(x)); return y;
}
__device__ __forceinline__ float fast_sigmoid(float x) {
    return 0.5f * fast_tanh(0.5f * x) + 0.5f;
}
// packed fp32x2 helpers (Blackwell)
__device__ __forceinline__ u64 pack2(float x) {
    u64 r; asm("mov.b64 %0, {%1, %1};" : "=l"(r) : "f"(x)); return r;
}
__device__ __forceinline__ void fma2(u64 &acc, u64 w, u64 h) {
    asm("fma.rn.f32x2 %0, %1, %2, %3;" : "=l"(acc) : "l"(w), "l"(h), "l"(acc));
}
__device__ __forceinline__ float2 unpack2(u64 v) {
    float2 f; asm("mov.b64 {%0, %1}, %2;" : "=f"(f.x), "=f"(f.y) : "l"(v)); return f;
}

// ---------------- K0: prep — W_beta interleave + zero g_emb ----------------
__global__ void k_prep(const float* __restrict__ W_beta) {
    int idx = blockIdx.x * 256 + threadIdx.x;
    if (idx < E_ * E_) {
        int kk = idx >> 7, e = idx & 127;
        g_Wbeta2[kk * 128 + ((e & 31) << 2) + (e >> 5)] = W_beta[e * E_ + kk];
    } else {
        int z = idx - E_ * E_;
        if (z < BT * E_) g_emb[z] = 0.f;
    }
}

// ---------------- K1: embedding GEMM  emb += x @ W_emb^T (split-K2) --------
__global__ void __launch_bounds__(256) k_embed(const float* __restrict__ x,
                                               const float* __restrict__ Wemb) {
    __shared__ float As[32][36];
    __shared__ float Bs[32][132];
    const int m0   = blockIdx.x * 32;
    const int kbeg = blockIdx.y * 2448;
    const int kend = (kbeg + 2448 < IND) ? (kbeg + 2448) : IND;
    const int tid  = threadIdx.x;
    const int tx   = tid & 31;
    const int ty   = tid >> 5;
    float acc[4][4];
#pragma unroll
    for (int a = 0; a < 4; a++)
#pragma unroll
        for (int b = 0; b < 4; b++) acc[a][b] = 0.f;

    float pa[4], pb[16];
    {
#pragma unroll
        for (int u = 0; u < 4; u++) {
            int l = tid + 256 * u, kk = l & 31, mm = l >> 5, k = kbeg + kk;
            pa[u] = (k < kend) ? x[(m0 + mm) * IND + k] : 0.f;
        }
#pragma unroll
        for (int u = 0; u < 16; u++) {
            int l = tid + 256 * u, kk = l & 31, ee = l >> 5, k = kbeg + kk;
            pb[u] = (k < kend) ? Wemb[ee * IND + k] : 0.f;
        }
    }
    for (int k0 = kbeg; k0 < kend; k0 += 32) {
        __syncthreads();
#pragma unroll
        for (int u = 0; u < 4; u++) {
            int l = tid + 256 * u;
            As[l & 31][l >> 5] = pa[u];
        }
#pragma unroll
        for (int u = 0; u < 16; u++) {
            int l = tid + 256 * u;
            Bs[l & 31][l >> 5] = pb[u];
        }
        __syncthreads();
        int kn = k0 + 32;
        if (kn < kend) {
#pragma unroll
            for (int u = 0; u < 4; u++) {
                int l = tid + 256 * u, kk = l & 31, mm = l >> 5, k = kn + kk;
                pa[u] = (k < kend) ? x[(m0 + mm) * IND + k] : 0.f;
            }
#pragma unroll
            for (int u = 0; u < 16; u++) {
                int l = tid + 256 * u, kk = l & 31, ee = l >> 5, k = kn + kk;
                pb[u] = (k < kend) ? Wemb[ee * IND + k] : 0.f;
            }
        }
#pragma unroll
        for (int kk = 0; kk < 32; kk++) {
            float4 av = *(const float4*)&As[kk][ty * 4];
            float4 bv = *(const float4*)&Bs[kk][tx * 4];
            float am[4] = {av.x, av.y, av.z, av.w};
            float bn[4] = {bv.x, bv.y, bv.z, bv.w};
#pragma unroll
            for (int a = 0; a < 4; a++)
#pragma unroll
                for (int b = 0; b < 4; b++) acc[a][b] += am[a] * bn[b];
        }
    }
#pragma unroll
    for (int a = 0; a < 4; a++)
#pragma unroll
        for (int b = 0; b < 4; b++)
            atomicAdd(&g_emb[(m0 + ty * 4 + a) * E_ + tx * 4 + b], acc[a][b]);
}

// ---------------- K2: GI = temb @ [Wih_a | Wih_b]^T + bih (+bhh for r,z) ----
__global__ void __launch_bounds__(256) k_gi(const float* __restrict__ tt,
                                            const float* __restrict__ Wih_a,
                                            const float* __restrict__ Wih_b,
                                            const float* __restrict__ bih_a,
                                            const float* __restrict__ bih_b,
                                            const float* __restrict__ bhh_a,
                                            const float* __restrict__ bhh_b) {
    __shared__ float As[64][33];
    __shared__ float Bs[64][68];
    const int m0  = blockIdx.x * 32;
    const int n0  = blockIdx.y * 64;
    const int tid = threadIdx.x;
    const int tx  = tid & 15;
    const int ty  = tid >> 4;
    float acc[2][4];
#pragma unroll
    for (int a = 0; a < 2; a++)
#pragma unroll
        for (int b = 0; b < 4; b++) acc[a][b] = 0.f;

    for (int k0 = 0; k0 < 129; k0 += 64) {
        for (int l = tid; l < 64 * 32; l += 256) {
            int kk = l & 63, mm = l >> 6;
            int k = k0 + kk;
            float v = 0.f;
            if (k < 128)       v = g_emb[(m0 + mm) * E_ + k];
            else if (k == 128) v = tt[m0 + mm];
            As[kk][mm] = v;
        }
        for (int l = tid; l < 64 * 64; l += 256) {
            int kk = l & 63, e = l >> 6;
            int k = k0 + kk;
            int g = n0 + e;
            float v = 0.f;
            if (k < 129)
                v = (g < G3) ? Wih_a[g * 129 + k] : Wih_b[(g - G3) * 129 + k];
            Bs[kk][e] = v;
        }
        __syncthreads();
#pragma unroll 8
        for (int kk = 0; kk < 64; kk++) {
            float a0 = As[kk][ty * 2];
            float a1 = As[kk][ty * 2 + 1];
            float4 bv = *(const float4*)&Bs[kk][tx * 4];
            acc[0][0] += a0 * bv.x; acc[0][1] += a0 * bv.y;
            acc[0][2] += a0 * bv.z; acc[0][3] += a0 * bv.w;
            acc[1][0] += a1 * bv.x; acc[1][1] += a1 * bv.y;
            acc[1][2] += a1 * bv.z; acc[1][3] += a1 * bv.w;
        }
        __syncthreads();
    }
#pragma unroll
    for (int a = 0; a < 2; a++)
#pragma unroll
        for (int b = 0; b < 4; b++) {
            int g  = n0 + tx * 4 + b;
            int gg = (g < G3) ? g : g - G3;
            float bias = (g < G3) ? bih_a[gg] : bih_b[gg];
            if (gg < 256)
                bias += (g < G3) ? bhh_a[gg] : bhh_b[gg];
            g_GI[(m0 + ty * 2 + a) * NG + g] = acc[a][b] + bias;
        }
}

// ---------------- K3: GRU recurrence — 32 batch rows/step, packed f32x2 -----
// 128 CTAs: (gru = bx&1, query i = bx>>1). Wall = 64-step CTA. Whh in smem.
// Single-buffered h (2 barriers/step). Thread = (q = tid>>7 -> rows 16q..16q+15,
// e = tid&127 owns gate column e of all 3 gates).
__global__ void __launch_bounds__(256, 1)
k_gru(const float* __restrict__ Whh_a, const float* __restrict__ Whh_b,
      const float* __restrict__ bhh_a, const float* __restrict__ bhh_b,
      const float* __restrict__ w_alpha, const float* __restrict__ b_alpha)
{
    extern __shared__ float ws[];       // [384][WPAD]
    __shared__ float sh_h[E_][HST];     // [hdim][row32 + pad]
    __shared__ float sh_wal[E_];
    __shared__ float sh_bal;

    const int tid = threadIdx.x;
    const int gru = blockIdx.x & 1;
    const int i   = blockIdx.x >> 1;    // query 0..63
    const int q   = tid >> 7;           // 0/1 -> rows 16q..16q+15
    const int e   = tid & 127;

    const float* __restrict__ W = gru ? Whh_b : Whh_a;   // [384][128]
    for (int l = tid; l < G3 * E_; l += 256)
        ws[(l >> 7) * WPAD + (l & 127)] = W[l];
    if (tid < E_) sh_wal[tid] = w_alpha[tid];
    if (tid == 0) sh_bal = b_alpha[0];
    const float bhhn = (gru ? bhh_b : bhh_a)[256 + e];

    const float* __restrict__ wrp = ws + e * WPAD;
    const float* __restrict__ wzp = ws + (e + 128) * WPAD;
    const float* __restrict__ wnp = ws + (e + 256) * WPAD;

    for (int l = tid; l < E_ * HST; l += 256) (&sh_h[0][0])[l] = 0.f;
    __syncthreads();

    for (int k = 0; k <= i; k++) {
        const int j = i - k;

        // GI loads (global, independent of h -> issued before the GEMM)
        float gir[16], giz[16], gin[16];
        {
            const float* gp = g_GI + ((16 * q) * T_ + j) * NG + gru * G3 + e;
#pragma unroll
            for (int rr = 0; rr < 16; rr++) {
                gir[rr] = gp[0]; giz[rr] = gp[128]; gin[rr] = gp[256];
                gp += T_ * NG;
            }
        }

        // gh GEMM: 16 rows x 3 gates, packed f32x2, h broadcast from smem
        u64 aR2[8], aZ2[8], aN2[8];
#pragma unroll
        for (int p = 0; p < 8; p++) { aR2[p] = 0ULL; aZ2[p] = 0ULL; aN2[p] = 0ULL; }
#pragma unroll 2
        for (int kq = 0; kq < 32; kq++) {
            const int kk = kq * 4;
            float4 r4 = *(const float4*)(wrp + kk);
            float4 z4 = *(const float4*)(wzp + kk);
            float4 n4 = *(const float4*)(wnp + kk);
            const float wrs[4] = {r4.x, r4.y, r4.z, r4.w};
            const float wzs[4] = {z4.x, z4.y, z4.z, z4.w};
            const float wns[4] = {n4.x, n4.y, n4.z, n4.w};
#pragma unroll
            for (int s = 0; s < 4; s++) {
                const float* hp = &sh_h[kk + s][16 * q];
                ulonglong2 hA = *(const ulonglong2*)(hp);
                ulonglong2 hB = *(const ulonglong2*)(hp + 4);
                ulonglong2 hC = *(const ulonglong2*)(hp + 8);
                ulonglong2 hD = *(const ulonglong2*)(hp + 12);
                u64 w2;
                w2 = pack2(wrs[s]);
                fma2(aR2[0], w2, hA.x); fma2(aR2[1], w2, hA.y);
                fma2(aR2[2], w2, hB.x); fma2(aR2[3], w2, hB.y);
                fma2(aR2[4], w2, hC.x); fma2(aR2[5], w2, hC.y);
                fma2(aR2[6], w2, hD.x); fma2(aR2[7], w2, hD.y);
                w2 = pack2(wzs[s]);
                fma2(aZ2[0], w2, hA.x); fma2(aZ2[1], w2, hA.y);
                fma2(aZ2[2], w2, hB.x); fma2(aZ2[3], w2, hB.y);
                fma2(aZ2[4], w2, hC.x); fma2(aZ2[5], w2, hC.y);
                fma2(aZ2[6], w2, hD.x); fma2(aZ2[7], w2, hD.y);
                w2 = pack2(wns[s]);
                fma2(aN2[0], w2, hA.x); fma2(aN2[1], w2, hA.y);
                fma2(aN2[2], w2, hB.x); fma2(aN2[3], w2, hB.y);
                fma2(aN2[4], w2, hC.x); fma2(aN2[5], w2, hC.y);
                fma2(aN2[6], w2, hD.x); fma2(aN2[7], w2, hD.y);
            }
        }

        // gate combine in registers
        float hn[16];
        {
            float4 ho0 = *(const float4*)(&sh_h[e][16 * q]);
            float4 ho1 = *(const float4*)(&sh_h[e][16 * q + 4]);
            float4 ho2 = *(const float4*)(&sh_h[e][16 * q + 8]);
            float4 ho3 = *(const float4*)(&sh_h[e][16 * q + 12]);
            float ho[16] = {ho0.x, ho0.y, ho0.z, ho0.w, ho1.x, ho1.y, ho1.z, ho1.w,
                            ho2.x, ho2.y, ho2.z, ho2.w, ho3.x, ho3.y, ho3.z, ho3.w};
#pragma unroll
            for (int p = 0; p < 8; p++) {
                float2 vr = unpack2(aR2[p]);
                float2 vz = unpack2(aZ2[p]);
                float2 vn = unpack2(aN2[p]);
                float a_r[2] = {vr.x, vr.y}, a_z[2] = {vz.x, vz.y}, a_n[2] = {vn.x, vn.y};
#pragma unroll
                for (int t = 0; t < 2; t++) {
                    int rr = 2 * p + t;
                    float rg = fast_sigmoid(gir[rr] + a_r[t]);   // bhh_r in GI
                    float zg = fast_sigmoid(giz[rr] + a_z[t]);   // bhh_z in GI
                    float ng = fast_tanh(gin[rr] + rg * (a_n[t] + bhhn));
                    hn[rr] = (1.f - zg) * ng + zg * ho[rr];
                }
            }
        }
        __syncthreads();    // bar A: all reads of old h complete

        // write h_new; GRU-b emits hb rows
        *(float4*)(&sh_h[e][16 * q])      = make_float4(hn[0],  hn[1],  hn[2],  hn[3]);
        *(float4*)(&sh_h[e][16 * q + 4])  = make_float4(hn[4],  hn[5],  hn[6],  hn[7]);
        *(float4*)(&sh_h[e][16 * q + 8])  = make_float4(hn[8],  hn[9],  hn[10], hn[11]);
        *(float4*)(&sh_h[e][16 * q + 12]) = make_float4(hn[12], hn[13], hn[14], hn[15]);
        if (gru) {
#pragma unroll
            for (int rr = 0; rr < 16; rr++) {
                int b = 16 * q + rr;
                g_Hb[((b * T_ + i) * T_ + k) * E_ + e] = hn[rr];
            }
        }
        __syncthreads();    // bar B: h_new visible to all

        // GRU-a: scores for rows 4w..4w+3 (warp w)
        if (!gru) {
            const int w = tid >> 5, lane = tid & 31;
            float p0 = 0.f, p1 = 0.f, p2 = 0.f, p3 = 0.f;
#pragma unroll
            for (int qq = 0; qq < 4; qq++) {
                int ee = lane + 32 * qq;
                float wv = sh_wal[ee];
                p0 += sh_h[ee][4 * w]     * wv;
                p1 += sh_h[ee][4 * w + 1] * wv;
                p2 += sh_h[ee][4 * w + 2] * wv;
                p3 += sh_h[ee][4 * w + 3] * wv;
            }
#pragma unroll
            for (int o = 16; o; o >>= 1) {
                p0 += __shfl_xor_sync(0xffffffffu, p0, o);
                p1 += __shfl_xor_sync(0xffffffffu, p1, o);
                p2 += __shfl_xor_sync(0xffffffffu, p2, o);
                p3 += __shfl_xor_sync(0xffffffffu, p3, o);
            }
            if (lane == 0) {
                g_S[((4 * w)     * T_ + i) * T_ + k] = p0 + sh_bal;
                g_S[((4 * w + 1) * T_ + i) * T_ + k] = p1 + sh_bal;
                g_S[((4 * w + 2) * T_ + i) * T_ + k] = p2 + sh_bal;
                g_S[((4 * w + 3) * T_ + i) * T_ + k] = p3 + sh_bal;
            }
        }
    }
}

// ---------------- K4: beta GEMM + softmax + output --------------------------
// Block = (b, i-quad); 512 blocks. 4 k-rows per warp (4x Wbeta LDS reuse).
__global__ void __launch_bounds__(256)
k_attn(const float* __restrict__ b_beta, const float* __restrict__ W_out,
       const float* __restrict__ b_out,  const int* __restrict__ lengths,
       float* __restrict__ out)
{
    extern __shared__ float wsb[];      // [kk][lane*4+q]  16384 floats
    __shared__ float hb_s[32][E_];      // 32 k-rows
    __shared__ float u_s[T_];
    __shared__ float s_bbe[E_], s_wout[E_];

    const int blk  = blockIdx.x;
    const int b    = blk >> 4;
    const int iq   = blk & 15;
    const int tid  = threadIdx.x;
    const int wrp  = tid >> 5;          // warp 0..7
    const int lane = tid & 31;

    for (int l = tid; l < E_ * E_ / 4; l += 256)
        ((float4*)wsb)[l] = ((const float4*)g_Wbeta2)[l];
    if (tid < E_) { s_bbe[tid] = b_beta[tid]; s_wout[tid] = W_out[tid]; }
    __syncthreads();

    const int ilist[4] = {iq, 63 - iq, 16 + iq, 47 - iq};

    for (int iv = 0; iv < 4; iv++) {
        const int i = ilist[iv];

        for (int kt = 0; kt <= i; kt += 32) {
            for (int l = tid; l < 32 * 32; l += 256) {
                int r = l >> 5, e4 = (l & 31) << 2;
                int k = kt + r;
                float4 v = make_float4(0.f, 0.f, 0.f, 0.f);
                if (k <= i)
                    v = *(const float4*)&g_Hb[((b * T_ + i) * T_ + k) * E_ + e4];
                *(float4*)&hb_s[r][e4] = v;
            }
            __syncthreads();

            const int kb = kt + wrp * 4;
            if (kb <= i) {
                float d[4][4];
#pragma unroll
                for (int t = 0; t < 4; t++)
#pragma unroll
                    for (int g = 0; g < 4; g++) d[t][g] = 0.f;
                const float* __restrict__ wb = wsb + (lane << 2);
                const int r0 = wrp * 4;
#pragma unroll 4
                for (int kk = 0; kk < E_; kk++) {
                    float4 wv = *(const float4*)(wb + kk * 128);
                    float h0 = hb_s[r0][kk];
                    float h1 = hb_s[r0 + 1][kk];
                    float h2 = hb_s[r0 + 2][kk];
                    float h3 = hb_s[r0 + 3][kk];
                    d[0][0] += h0 * wv.x; d[0][1] += h0 * wv.y; d[0][2] += h0 * wv.z; d[0][3] += h0 * wv.w;
                    d[1][0] += h1 * wv.x; d[1][1] += h1 * wv.y; d[1][2] += h1 * wv.z; d[1][3] += h1 * wv.w;
                    d[2][0] += h2 * wv.x; d[2][1] += h2 * wv.y; d[2][2] += h2 * wv.z; d[2][3] += h2 * wv.w;
                    d[3][0] += h3 * wv.x; d[3][1] += h3 * wv.y; d[3][2] += h3 * wv.z; d[3][3] += h3 * wv.w;
                }
#pragma unroll
                for (int t = 0; t < 4; t++) {
                    const int k = kb + t;
                    if (k <= i) {
                        const int j = i - k;
                        const float* ep = g_emb + (b * T_ + j) * E_ + lane;
                        float u = fast_tanh(d[t][0] + s_bbe[lane])      * ep[0]  * s_wout[lane]
                                + fast_tanh(d[t][1] + s_bbe[lane + 32]) * ep[32] * s_wout[lane + 32]
                                + fast_tanh(d[t][2] + s_bbe[lane + 64]) * ep[64] * s_wout[lane + 64]
                                + fast_tanh(d[t][3] + s_bbe[lane + 96]) * ep[96] * s_wout[lane + 96];
#pragma unroll
                        for (int o = 16; o; o >>= 1)
                            u += __shfl_xor_sync(0xffffffffu, u, o);
                        if (lane == 0) u_s[k] = u;
                    }
                }
            }
            __syncthreads();
        }

        if (wrp == 0) {
            const float* sp = g_S + (b * T_ + i) * T_;
            float s0 = (lane <= i)      ? sp[lane]      : -INFINITY;
            float s1 = (lane + 32 <= i) ? sp[lane + 32] : -INFINITY;
            float mx = fmaxf(s0, s1);
#pragma unroll
            for (int o = 16; o; o >>= 1)
                mx = fmaxf(mx, __shfl_xor_sync(0xffffffffu, mx, o));
            float e0 = (lane <= i)      ? __expf(s0 - mx) : 0.f;
            float e1 = (lane + 32 <= i) ? __expf(s1 - mx) : 0.f;
            float num = e0 * ((lane <= i)      ? u_s[lane]      : 0.f)
                      + e1 * ((lane + 32 <= i) ? u_s[lane + 32] : 0.f);
            float den = e0 + e1;
#pragma unroll
            for (int o = 16; o; o >>= 1) {
                num += __shfl_xor_sync(0xffffffffu, num, o);
                den += __shfl_xor_sync(0xffffffffu, den, o);
            }
            if (lane == 0) {
                float valid = (i < lengths[b]) ? 1.f : 0.f;
                out[b * T_ + i] = (num / den) * valid + b_out[0];
            }
        }
        __syncthreads();
    }
}

// ---------------- launch ----------------
extern "C" void kernel_launch(void* const* d_in, const int* in_sizes, int n_in,
                              void* d_out, int out_size) {
    const float* x       = (const float*)d_in[0];
    const float* tt      = (const float*)d_in[1];
    const int*   lengths = (const int*)  d_in[2];
    const float* Wemb    = (const float*)d_in[3];
    const float* Wih_a   = (const float*)d_in[4];
    const float* Whh_a   = (const float*)d_in[5];
    const float* bih_a   = (const float*)d_in[6];
    const float* bhh_a   = (const float*)d_in[7];
    const float* Wih_b   = (const float*)d_in[8];
    const float* Whh_b   = (const float*)d_in[9];
    const float* bih_b   = (const float*)d_in[10];
    const float* bhh_b   = (const float*)d_in[11];
    const float* w_alpha = (const float*)d_in[12];
    const float* b_alpha = (const float*)d_in[13];
    const float* W_beta  = (const float*)d_in[14];
    const float* b_beta  = (const float*)d_in[15];
    const float* W_out   = (const float*)d_in[16];
    const float* b_out   = (const float*)d_in[17];
    float* out = (float*)d_out;

    cudaFuncSetAttribute(k_gru, cudaFuncAttributeMaxDynamicSharedMemorySize,
                         GRU_SMEM);
    cudaFuncSetAttribute(k_attn, cudaFuncAttributeMaxDynamicSharedMemorySize,
                         ATTN_SMEM);

    k_prep<<<1088, 256>>>(W_beta);
    k_embed<<<dim3(64, 2), 256>>>(x, Wemb);
    k_gi<<<dim3(64, 12), 256>>>(tt, Wih_a, Wih_b, bih_a, bih_b, bhh_a, bhh_b);
    k_gru<<<128, 256, GRU_SMEM>>>(Whh_a, Whh_b, bhh_a, bhh_b, w_alpha, b_alpha);
    k_attn<<<512, 256, ATTN_SMEM>>>(b_beta, W_out, b_out, lengths, out);
}

// round 17
// speedup vs baseline: 1.4272x; 1.4272x over previous
#include <cuda_runtime.h>
#include <math.h>

#define B_   32
#define T_   64
#define BT   2048            // B*T
#define IND  4894
#define E_   128
#define G3   384             // 3*H
#define NG   768             // both GRUs' gates
#define WPAD 132             // smem stride for Whh rows (conflict-free float4)
#define GRU_SMEM  (G3 * WPAD * 4)    // 202752 B
#define ATTN_SMEM (E_ * E_ * 4)      // 65536 B (W_beta interleaved)

typedef unsigned long long u64;

// ---------------- device scratch (no allocations allowed) ----------------
__device__ float g_emb[BT * E_];        // emb[m][e]  (atomicAdd target)
__device__ float g_GI [BT * NG];        // input gates + bih (+ bhh for r,z)
__device__ float g_Wbeta2[E_ * E_];     // [kk][(e&31)*4 + (e>>5)]
__device__ float g_Hb[BT * T_ * E_];    // hb states [b][i][k][e]
__device__ float g_S [BT * T_];         // scores [b][i][k]

__device__ __forceinline__ float fast_tanh(float x) {
    float y; asm("tanh.approx.f32 %0, %1;" : "=f"(y) : "f"(x)); return y;
}
__device__ __forceinline__ float fast_sigmoid(float x) {
    return 0.5f * fast_tanh(0.5f * x) + 0.5f;
}
// packed fp32x2 helpers (Blackwell)
__device__ __forceinline__ u64 pack2(float x) {
    u64 r; asm("mov.b64 %0, {%1, %1};" : "=l"(r) : "f"(x)); return r;
}
__device__ __forceinline__ void fma2(u64 &acc, u64 w, u64 h) {
    asm("fma.rn.f32x2 %0, %1, %2, %3;" : "=l"(acc) : "l"(w), "l"(h), "l"(acc));
}
__device__ __forceinline__ float2 unpack2(u64 v) {
    float2 f; asm("mov.b64 {%0, %1}, %2;" : "=f"(f.x), "=f"(f.y) : "l"(v)); return f;
}

// ---------------- K0: prep — W_beta interleave + zero g_emb ----------------
__global__ void k_prep(const float* __restrict__ W_beta) {
    int idx = blockIdx.x * 256 + threadIdx.x;
    if (idx < E_ * E_) {
        int kk = idx >> 7, e = idx & 127;
        g_Wbeta2[kk * 128 + ((e & 31) << 2) + (e >> 5)] = W_beta[e * E_ + kk];
    } else {
        int z = idx - E_ * E_;
        if (z < BT * E_) g_emb[z] = 0.f;
    }
}

// ---------------- K1: embedding GEMM  emb += x @ W_emb^T (split-K2, fma2) ---
__global__ void __launch_bounds__(256) k_embed(const float* __restrict__ x,
                                               const float* __restrict__ Wemb) {
    __shared__ float As[32][36];
    __shared__ float Bs[32][132];
    const int m0   = blockIdx.x * 32;
    const int kbeg = blockIdx.y * 2448;
    const int kend = (kbeg + 2448 < IND) ? (kbeg + 2448) : IND;
    const int tid  = threadIdx.x;
    const int tx   = tid & 31;
    const int ty   = tid >> 5;
    u64 acc2[4][2];           // [a][pair of n]
#pragma unroll
    for (int a = 0; a < 4; a++) { acc2[a][0] = 0ULL; acc2[a][1] = 0ULL; }

    float pa[4], pb[16];
    {
#pragma unroll
        for (int u = 0; u < 4; u++) {
            int l = tid + 256 * u, kk = l & 31, mm = l >> 5, k = kbeg + kk;
            pa[u] = (k < kend) ? x[(m0 + mm) * IND + k] : 0.f;
        }
#pragma unroll
        for (int u = 0; u < 16; u++) {
            int l = tid + 256 * u, kk = l & 31, ee = l >> 5, k = kbeg + kk;
            pb[u] = (k < kend) ? Wemb[ee * IND + k] : 0.f;
        }
    }
    for (int k0 = kbeg; k0 < kend; k0 += 32) {
        __syncthreads();
#pragma unroll
        for (int u = 0; u < 4; u++) {
            int l = tid + 256 * u;
            As[l & 31][l >> 5] = pa[u];
        }
#pragma unroll
        for (int u = 0; u < 16; u++) {
            int l = tid + 256 * u;
            Bs[l & 31][l >> 5] = pb[u];
        }
        __syncthreads();
        int kn = k0 + 32;
        if (kn < kend) {
#pragma unroll
            for (int u = 0; u < 4; u++) {
                int l = tid + 256 * u, kk = l & 31, mm = l >> 5, k = kn + kk;
                pa[u] = (k < kend) ? x[(m0 + mm) * IND + k] : 0.f;
            }
#pragma unroll
            for (int u = 0; u < 16; u++) {
                int l = tid + 256 * u, kk = l & 31, ee = l >> 5, k = kn + kk;
                pb[u] = (k < kend) ? Wemb[ee * IND + k] : 0.f;
            }
        }
#pragma unroll
        for (int kk = 0; kk < 32; kk++) {
            float4 av = *(const float4*)&As[kk][ty * 4];
            ulonglong2 bv2 = *(const ulonglong2*)&Bs[kk][tx * 4];
            u64 a0 = pack2(av.x), a1 = pack2(av.y), a2 = pack2(av.z), a3 = pack2(av.w);
            fma2(acc2[0][0], a0, bv2.x); fma2(acc2[0][1], a0, bv2.y);
            fma2(acc2[1][0], a1, bv2.x); fma2(acc2[1][1], a1, bv2.y);
            fma2(acc2[2][0], a2, bv2.x); fma2(acc2[2][1], a2, bv2.y);
            fma2(acc2[3][0], a3, bv2.x); fma2(acc2[3][1], a3, bv2.y);
        }
    }
#pragma unroll
    for (int a = 0; a < 4; a++) {
        float2 v0 = unpack2(acc2[a][0]);
        float2 v1 = unpack2(acc2[a][1]);
        float* dst = &g_emb[(m0 + ty * 4 + a) * E_ + tx * 4];
        atomicAdd(dst,     v0.x);
        atomicAdd(dst + 1, v0.y);
        atomicAdd(dst + 2, v1.x);
        atomicAdd(dst + 3, v1.y);
    }
}

// ---------------- K2: GI = temb @ [Wih_a | Wih_b]^T + bih (+bhh for r,z) ----
__global__ void __launch_bounds__(256) k_gi(const float* __restrict__ tt,
                                            const float* __restrict__ Wih_a,
                                            const float* __restrict__ Wih_b,
                                            const float* __restrict__ bih_a,
                                            const float* __restrict__ bih_b,
                                            const float* __restrict__ bhh_a,
                                            const float* __restrict__ bhh_b) {
    __shared__ float As[64][33];
    __shared__ float Bs[64][68];
    const int m0  = blockIdx.x * 32;
    const int n0  = blockIdx.y * 64;
    const int tid = threadIdx.x;
    const int tx  = tid & 15;
    const int ty  = tid >> 4;
    float acc[2][4];
#pragma unroll
    for (int a = 0; a < 2; a++)
#pragma unroll
        for (int b = 0; b < 4; b++) acc[a][b] = 0.f;

    for (int k0 = 0; k0 < 129; k0 += 64) {
        for (int l = tid; l < 64 * 32; l += 256) {
            int kk = l & 63, mm = l >> 6;
            int k = k0 + kk;
            float v = 0.f;
            if (k < 128)       v = g_emb[(m0 + mm) * E_ + k];
            else if (k == 128) v = tt[m0 + mm];
            As[kk][mm] = v;
        }
        for (int l = tid; l < 64 * 64; l += 256) {
            int kk = l & 63, e = l >> 6;
            int k = k0 + kk;
            int g = n0 + e;
            float v = 0.f;
            if (k < 129)
                v = (g < G3) ? Wih_a[g * 129 + k] : Wih_b[(g - G3) * 129 + k];
            Bs[kk][e] = v;
        }
        __syncthreads();
#pragma unroll 8
        for (int kk = 0; kk < 64; kk++) {
            float a0 = As[kk][ty * 2];
            float a1 = As[kk][ty * 2 + 1];
            float4 bv = *(const float4*)&Bs[kk][tx * 4];
            acc[0][0] += a0 * bv.x; acc[0][1] += a0 * bv.y;
            acc[0][2] += a0 * bv.z; acc[0][3] += a0 * bv.w;
            acc[1][0] += a1 * bv.x; acc[1][1] += a1 * bv.y;
            acc[1][2] += a1 * bv.z; acc[1][3] += a1 * bv.w;
        }
        __syncthreads();
    }
#pragma unroll
    for (int a = 0; a < 2; a++)
#pragma unroll
        for (int b = 0; b < 4; b++) {
            int g  = n0 + tx * 4 + b;
            int gg = (g < G3) ? g : g - G3;
            float bias = (g < G3) ? bih_a[gg] : bih_b[gg];
            if (gg < 256)
                bias += (g < G3) ? bhh_a[gg] : bhh_b[gg];
            g_GI[(m0 + ty * 2 + a) * NG + g] = acc[a][b] + bias;
        }
}

// ---------------- K3: GRU recurrence (R14 schedule) + weight prefetch -------
// 128 CTAs (64 per GRU). Item = (query i, batch-half of 16). CTA c runs items
// {c, 127-c} -> exactly 65 steps per CTA. Whh fully in smem.
__global__ void __launch_bounds__(256, 1)
k_gru(const float* __restrict__ Whh_a, const float* __restrict__ Whh_b,
      const float* __restrict__ bhh_a, const float* __restrict__ bhh_b,
      const float* __restrict__ w_alpha, const float* __restrict__ b_alpha)
{
    extern __shared__ float ws[];       // [384][WPAD]
    __shared__ float sh_h[2][E_][20];   // [buf][hdim][row16 + pad4]
    __shared__ float sh_wal[E_];
    __shared__ float sh_bal;

    const int tid = threadIdx.x;
    const int gru = blockIdx.x & 1;
    const int c   = blockIdx.x >> 1;    // 0..63
    const int q   = tid >> 7;           // 0/1 -> rows 8q..8q+7
    const int e   = tid & 127;

    const float* __restrict__ W = gru ? Whh_b : Whh_a;   // [384][128]
    for (int l = tid; l < G3 * E_; l += 256)
        ws[(l >> 7) * WPAD + (l & 127)] = W[l];
    if (tid < E_) sh_wal[tid] = w_alpha[tid];
    if (tid == 0) sh_bal = b_alpha[0];
    const float bhhn = (gru ? bhh_b : bhh_a)[256 + e];

    const float* __restrict__ wrp = ws + e * WPAD;
    const float* __restrict__ wzp = ws + (e + 128) * WPAD;
    const float* __restrict__ wnp = ws + (e + 256) * WPAD;

    for (int it = 0; it < 2; it++) {
        const int idx  = it ? (127 - c) : c;
        const int i    = 63 - (idx >> 1);
        const int half = idx & 1;
        const int b0   = half * 16;     // batches b0..b0+15

        for (int l = tid; l < E_ * 20; l += 256) (&sh_h[1][0][0])[l] = 0.f;
        __syncthreads();

        for (int k = 0; k <= i; k++) {
            const int j = i - k;
            const int cur = k & 1, prev = cur ^ 1;

            // GI loads (independent of h; hidden under GEMM)
            float gir[8], giz[8], gin[8];
            {
                const float* gp = g_GI + ((b0 + 8 * q) * T_ + j) * NG + gru * G3 + e;
#pragma unroll
                for (int rr = 0; rr < 8; rr++) {
                    gir[rr] = gp[0]; giz[rr] = gp[128]; gin[rr] = gp[256];
                    gp += T_ * NG;
                }
            }

            // gh GEMM: 8 rows x 3 gates, packed f32x2; weights prefetched 1 kq ahead
            u64 aR2[4], aZ2[4], aN2[4];
#pragma unroll
            for (int p = 0; p < 4; p++) { aR2[p] = 0ULL; aZ2[p] = 0ULL; aN2[p] = 0ULL; }
            const float* hb_ = &sh_h[prev][0][0] + 8 * q;

            float4 r4 = *(const float4*)(wrp);
            float4 z4 = *(const float4*)(wzp);
            float4 n4 = *(const float4*)(wnp);
#pragma unroll 4
            for (int kq = 0; kq < 32; kq++) {
                const int kk = kq * 4;
                const int kn = (kq < 31) ? (kk + 4) : 0;
                float4 nr4 = *(const float4*)(wrp + kn);
                float4 nz4 = *(const float4*)(wzp + kn);
                float4 nn4 = *(const float4*)(wnp + kn);
                const float wrs[4] = {r4.x, r4.y, r4.z, r4.w};
                const float wzs[4] = {z4.x, z4.y, z4.z, z4.w};
                const float wns[4] = {n4.x, n4.y, n4.z, n4.w};
#pragma unroll
                for (int s = 0; s < 4; s++) {
                    ulonglong2 hA = *(const ulonglong2*)(hb_ + (kk + s) * 20);
                    ulonglong2 hB = *(const ulonglong2*)(hb_ + (kk + s) * 20 + 4);
                    u64 w2;
                    w2 = pack2(wrs[s]);
                    fma2(aR2[0], w2, hA.x); fma2(aR2[1], w2, hA.y);
                    fma2(aR2[2], w2, hB.x); fma2(aR2[3], w2, hB.y);
                    w2 = pack2(wzs[s]);
                    fma2(aZ2[0], w2, hA.x); fma2(aZ2[1], w2, hA.y);
                    fma2(aZ2[2], w2, hB.x); fma2(aZ2[3], w2, hB.y);
                    w2 = pack2(wns[s]);
                    fma2(aN2[0], w2, hA.x); fma2(aN2[1], w2, hA.y);
                    fma2(aN2[2], w2, hB.x); fma2(aN2[3], w2, hB.y);
                }
                r4 = nr4; z4 = nz4; n4 = nn4;
            }
            // unpack accumulators
            float aR[8], aZ[8], aN[8];
#pragma unroll
            for (int p = 0; p < 4; p++) {
                float2 v;
                v = unpack2(aR2[p]); aR[2*p] = v.x; aR[2*p+1] = v.y;
                v = unpack2(aZ2[p]); aZ[2*p] = v.x; aZ[2*p+1] = v.y;
                v = unpack2(aN2[p]); aN[2*p] = v.x; aN[2*p+1] = v.y;
            }

            // gate combine; write h_new; GRU-b emits hb rows
            {
                float4 ho0 = *(const float4*)(&sh_h[prev][e][8 * q]);
                float4 ho1 = *(const float4*)(&sh_h[prev][e][8 * q + 4]);
                float ho[8] = {ho0.x, ho0.y, ho0.z, ho0.w, ho1.x, ho1.y, ho1.z, ho1.w};
                float hn[8];
#pragma unroll
                for (int rr = 0; rr < 8; rr++) {
                    float rg = fast_sigmoid(gir[rr] + aR[rr]);   // bhh_r in GI
                    float zg = fast_sigmoid(giz[rr] + aZ[rr]);   // bhh_z in GI
                    float ng = fast_tanh(gin[rr] + rg * (aN[rr] + bhhn));
                    hn[rr] = (1.f - zg) * ng + zg * ho[rr];
                }
                *(float4*)(&sh_h[cur][e][8 * q])     = make_float4(hn[0], hn[1], hn[2], hn[3]);
                *(float4*)(&sh_h[cur][e][8 * q + 4]) = make_float4(hn[4], hn[5], hn[6], hn[7]);
                if (gru) {
#pragma unroll
                    for (int rr = 0; rr < 8; rr++) {
                        int b = b0 + 8 * q + rr;
                        g_Hb[((b * T_ + i) * T_ + k) * E_ + e] = hn[rr];
                    }
                }
            }
            __syncthreads();

            // GRU-a: scores for rows 2w, 2w+1 (warp w)
            if (!gru) {
                const int w = tid >> 5, lane = tid & 31;
                const int r0 = 2 * w, r1 = 2 * w + 1;
                float p0 = 0.f, p1 = 0.f;
#pragma unroll
                for (int qq = 0; qq < 4; qq++) {
                    int ee = lane + 32 * qq;
                    float wv = sh_wal[ee];
                    p0 += sh_h[cur][ee][r0] * wv;
                    p1 += sh_h[cur][ee][r1] * wv;
                }
#pragma unroll
                for (int o = 16; o; o >>= 1) {
                    p0 += __shfl_xor_sync(0xffffffffu, p0, o);
                    p1 += __shfl_xor_sync(0xffffffffu, p1, o);
                }
                if (lane == 0) {
                    g_S[((b0 + r0) * T_ + i) * T_ + k] = p0 + sh_bal;
                    g_S[((b0 + r1) * T_ + i) * T_ + k] = p1 + sh_bal;
                }
            }
        }
        __syncthreads();    // protect sh_h before next item's zeroing
    }
}

// ---------------- K4: beta GEMM + softmax + output (packed fma2) ------------
// Block = (b, i-quad); 512 blocks. 4 k-rows per warp.
__global__ void __launch_bounds__(256)
k_attn(const float* __restrict__ b_beta, const float* __restrict__ W_out,
       const float* __restrict__ b_out,  const int* __restrict__ lengths,
       float* __restrict__ out)
{
    extern __shared__ float wsb[];      // [kk][lane*4+q]  16384 floats
    __shared__ float hb_s[32][E_];      // 32 k-rows
    __shared__ float u_s[T_];
    __shared__ float s_bbe[E_], s_wout[E_];

    const int blk  = blockIdx.x;
    const int b    = blk >> 4;
    const int iq   = blk & 15;
    const int tid  = threadIdx.x;
    const int wrp  = tid >> 5;          // warp 0..7
    const int lane = tid & 31;

    for (int l = tid; l < E_ * E_ / 4; l += 256)
        ((float4*)wsb)[l] = ((const float4*)g_Wbeta2)[l];
    if (tid < E_) { s_bbe[tid] = b_beta[tid]; s_wout[tid] = W_out[tid]; }
    __syncthreads();

    const int ilist[4] = {iq, 63 - iq, 16 + iq, 47 - iq};

    for (int iv = 0; iv < 4; iv++) {
        const int i = ilist[iv];

        for (int kt = 0; kt <= i; kt += 32) {
            for (int l = tid; l < 32 * 32; l += 256) {
                int r = l >> 5, e4 = (l & 31) << 2;
                int k = kt + r;
                float4 v = make_float4(0.f, 0.f, 0.f, 0.f);
                if (k <= i)
                    v = *(const float4*)&g_Hb[((b * T_ + i) * T_ + k) * E_ + e4];
                *(float4*)&hb_s[r][e4] = v;
            }
            __syncthreads();

            const int kb = kt + wrp * 4;
            if (kb <= i) {
                u64 d2[4][2];           // [t][gate-pair]
#pragma unroll
                for (int t = 0; t < 4; t++) { d2[t][0] = 0ULL; d2[t][1] = 0ULL; }
                const float* __restrict__ wb = wsb + (lane << 2);
                const int r0 = wrp * 4;
#pragma unroll 4
                for (int kk = 0; kk < E_; kk++) {
                    ulonglong2 wv2 = *(const ulonglong2*)(wb + kk * 128);
                    u64 h0 = pack2(hb_s[r0][kk]);
                    u64 h1 = pack2(hb_s[r0 + 1][kk]);
                    u64 h2 = pack2(hb_s[r0 + 2][kk]);
                    u64 h3 = pack2(hb_s[r0 + 3][kk]);
                    fma2(d2[0][0], h0, wv2.x); fma2(d2[0][1], h0, wv2.y);
                    fma2(d2[1][0], h1, wv2.x); fma2(d2[1][1], h1, wv2.y);
                    fma2(d2[2][0], h2, wv2.x); fma2(d2[2][1], h2, wv2.y);
                    fma2(d2[3][0], h3, wv2.x); fma2(d2[3][1], h3, wv2.y);
                }
#pragma unroll
                for (int t = 0; t < 4; t++) {
                    const int k = kb + t;
                    if (k <= i) {
                        float2 v0 = unpack2(d2[t][0]);
                        float2 v1 = unpack2(d2[t][1]);
                        const int j = i - k;
                        const float* ep = g_emb + (b * T_ + j) * E_ + lane;
                        float u = fast_tanh(v0.x + s_bbe[lane])      * ep[0]  * s_wout[lane]
                                + fast_tanh(v0.y + s_bbe[lane + 32]) * ep[32] * s_wout[lane + 32]
                                + fast_tanh(v1.x + s_bbe[lane + 64]) * ep[64] * s_wout[lane + 64]
                                + fast_tanh(v1.y + s_bbe[lane + 96]) * ep[96] * s_wout[lane + 96];
#pragma unroll
                        for (int o = 16; o; o >>= 1)
                            u += __shfl_xor_sync(0xffffffffu, u, o);
                        if (lane == 0) u_s[k] = u;
                    }
                }
            }
            __syncthreads();
        }

        if (wrp == 0) {
            const float* sp = g_S + (b * T_ + i) * T_;
            float s0 = (lane <= i)      ? sp[lane]      : -INFINITY;
            float s1 = (lane + 32 <= i) ? sp[lane + 32] : -INFINITY;
            float mx = fmaxf(s0, s1);
#pragma unroll
            for (int o = 16; o; o >>= 1)
                mx = fmaxf(mx, __shfl_xor_sync(0xffffffffu, mx, o));
            float e0 = (lane <= i)      ? __expf(s0 - mx) : 0.f;
            float e1 = (lane + 32 <= i) ? __expf(s1 - mx) : 0.f;
            float num = e0 * ((lane <= i)      ? u_s[lane]      : 0.f)
                      + e1 * ((lane + 32 <= i) ? u_s[lane + 32] : 0.f);
            float den = e0 + e1;
#pragma unroll
            for (int o = 16; o; o >>= 1) {
                num += __shfl_xor_sync(0xffffffffu, num, o);
                den += __shfl_xor_sync(0xffffffffu, den, o);
            }
            if (lane == 0) {
                float valid = (i < lengths[b]) ? 1.f : 0.f;
                out[b * T_ + i] = (num / den) * valid + b_out[0];
            }
        }
        __syncthreads();
    }
}

// ---------------- launch ----------------
extern "C" void kernel_launch(void* const* d_in, const int* in_sizes, int n_in,
                              void* d_out, int out_size) {
    const float* x       = (const float*)d_in[0];
    const float* tt      = (const float*)d_in[1];
    const int*   lengths = (const int*)  d_in[2];
    const float* Wemb    = (const float*)d_in[3];
    const float* Wih_a   = (const float*)d_in[4];
    const float* Whh_a   = (const float*)d_in[5];
    const float* bih_a   = (const float*)d_in[6];
    const float* bhh_a   = (const float*)d_in[7];
    const float* Wih_b   = (const float*)d_in[8];
    const float* Whh_b   = (const float*)d_in[9];
    const float* bih_b   = (const float*)d_in[10];
    const float* bhh_b   = (const float*)d_in[11];
    const float* w_alpha = (const float*)d_in[12];
    const float* b_alpha = (const float*)d_in[13];
    const float* W_beta  = (const float*)d_in[14];
    const float* b_beta  = (const float*)d_in[15];
    const float* W_out   = (const float*)d_in[16];
    const float* b_out   = (const float*)d_in[17];
    float* out = (float*)d_out;

    cudaFuncSetAttribute(k_gru, cudaFuncAttributeMaxDynamicSharedMemorySize,
                         GRU_SMEM);
    cudaFuncSetAttribute(k_attn, cudaFuncAttributeMaxDynamicSharedMemorySize,
                         ATTN_SMEM);

    k_prep<<<1088, 256>>>(W_beta);
    k_embed<<<dim3(64, 2), 256>>>(x, Wemb);
    k_gi<<<dim3(64, 12), 256>>>(tt, Wih_a, Wih_b, bih_a, bih_b, bhh_a, bhh_b);
    k_gru<<<128, 256, GRU_SMEM>>>(Whh_a, Whh_b, bhh_a, bhh_b, w_alpha, b_alpha);
    k_attn<<<512, 256, ATTN_SMEM>>>(b_beta, W_out, b_out, lengths, out);
}